// round 1
// baseline (speedup 1.0000x reference)
#include <cuda_runtime.h>
#include <cstdint>

// Problem shape (fixed by reference setup_inputs)
static constexpr int NB = 16;
static constexpr int TQ = 2048;
static constexpr int TS = 2048;
static constexpr int HD = 1024;

// 256 MB scratch for scores / softmax probabilities: S[b][q][s] (s contiguous)
__device__ float g_scores[(size_t)NB * TQ * TS];

__device__ __forceinline__ uint32_t f2tf(float x) {
    uint32_t u;
    asm("cvt.rna.tf32.f32 %0, %1;" : "=r"(u) : "f"(x));
    return u;
}

// m16n8k8 tf32 MMA, D = A*B + D
__device__ __forceinline__ void mma8(float c[4], const uint32_t a[4], const uint32_t b[2]) {
    asm volatile(
        "mma.sync.aligned.m16n8k8.row.col.f32.tf32.tf32.f32 "
        "{%0,%1,%2,%3}, {%4,%5,%6,%7}, {%8,%9}, {%0,%1,%2,%3};\n"
        : "+f"(c[0]), "+f"(c[1]), "+f"(c[2]), "+f"(c[3])
        : "r"(a[0]), "r"(a[1]), "r"(a[2]), "r"(a[3]), "r"(b[0]), "r"(b[1]));
}

// ============================================================================
// K1: scores[q,s] = sum_h hidden[q,h] * enc[s,h]   (NT GEMM, 3xTF32 split)
// Block tile 128x128, BK=16, 8 warps (2x4), warp tile 64x32, frag grid 4x4.
// ============================================================================
__global__ void __launch_bounds__(256)
scores_kernel(const float* __restrict__ hid, const float* __restrict__ enc) {
    __shared__ uint32_t AsH[128 * 20];
    __shared__ uint32_t AsL[128 * 20];
    __shared__ uint32_t BsH[128 * 20];
    __shared__ uint32_t BsL[128 * 20];

    const int bz = blockIdx.z;
    const float* A  = hid + (size_t)bz * TQ * HD;
    const float* Bm = enc + (size_t)bz * TS * HD;
    float* C = g_scores + (size_t)bz * TQ * TS;
    const int bM = blockIdx.y * 128;
    const int bN = blockIdx.x * 128;

    const int tid  = threadIdx.x;
    const int lane = tid & 31;
    const int wid  = tid >> 5;
    const int wm   = (wid >> 2) * 64;  // warp M offset (0 or 64)
    const int wn   = (wid & 3) * 32;   // warp N offset (0..96)
    const int tg   = lane & 3;         // threadID_in_group
    const int gp   = lane >> 2;        // groupID

    float acc[4][4][4];
    #pragma unroll
    for (int i = 0; i < 4; i++)
        #pragma unroll
        for (int j = 0; j < 4; j++)
            #pragma unroll
            for (int k = 0; k < 4; k++) acc[i][j][k] = 0.f;

    for (int k0 = 0; k0 < HD; k0 += 16) {
        // Load 128x16 tiles of A and B (both K-contiguous), split hi/lo tf32
        #pragma unroll
        for (int it = 0; it < 2; it++) {
            int slot = tid + it * 256;          // 0..511
            int r = slot >> 2;                  // 0..127
            int c = (slot & 3) * 4;             // 0,4,8,12
            float4 va = *reinterpret_cast<const float4*>(A  + (size_t)(bM + r) * HD + k0 + c);
            float4 vb = *reinterpret_cast<const float4*>(Bm + (size_t)(bN + r) * HD + k0 + c);
            float fa[4] = {va.x, va.y, va.z, va.w};
            float fb[4] = {vb.x, vb.y, vb.z, vb.w};
            #pragma unroll
            for (int j = 0; j < 4; j++) {
                uint32_t ha = f2tf(fa[j]);
                AsH[r * 20 + c + j] = ha;
                AsL[r * 20 + c + j] = f2tf(fa[j] - __uint_as_float(ha));
                uint32_t hb = f2tf(fb[j]);
                BsH[r * 20 + c + j] = hb;
                BsL[r * 20 + c + j] = f2tf(fb[j] - __uint_as_float(hb));
            }
        }
        __syncthreads();

        #pragma unroll
        for (int kk = 0; kk < 16; kk += 8) {
            uint32_t aH[4][4], aL[4][4], bH[4][2], bL[4][2];
            #pragma unroll
            for (int mf = 0; mf < 4; mf++) {
                int m = wm + mf * 16 + gp;
                aH[mf][0] = AsH[m * 20 + kk + tg];
                aH[mf][1] = AsH[(m + 8) * 20 + kk + tg];
                aH[mf][2] = AsH[m * 20 + kk + tg + 4];
                aH[mf][3] = AsH[(m + 8) * 20 + kk + tg + 4];
                aL[mf][0] = AsL[m * 20 + kk + tg];
                aL[mf][1] = AsL[(m + 8) * 20 + kk + tg];
                aL[mf][2] = AsL[m * 20 + kk + tg + 4];
                aL[mf][3] = AsL[(m + 8) * 20 + kk + tg + 4];
            }
            #pragma unroll
            for (int nf = 0; nf < 4; nf++) {
                int n = wn + nf * 8 + gp;
                bH[nf][0] = BsH[n * 20 + kk + tg];
                bH[nf][1] = BsH[n * 20 + kk + tg + 4];
                bL[nf][0] = BsL[n * 20 + kk + tg];
                bL[nf][1] = BsL[n * 20 + kk + tg + 4];
            }
            #pragma unroll
            for (int mf = 0; mf < 4; mf++)
                #pragma unroll
                for (int nf = 0; nf < 4; nf++) {
                    mma8(acc[mf][nf], aH[mf], bH[nf]);  // hi*hi
                    mma8(acc[mf][nf], aH[mf], bL[nf]);  // hi*lo
                    mma8(acc[mf][nf], aL[mf], bH[nf]);  // lo*hi
                }
        }
        __syncthreads();
    }

    #pragma unroll
    for (int mf = 0; mf < 4; mf++) {
        int r0 = bM + wm + mf * 16 + gp;
        #pragma unroll
        for (int nf = 0; nf < 4; nf++) {
            int c0 = bN + wn + nf * 8 + 2 * tg;
            *reinterpret_cast<float2*>(C + (size_t)r0 * TS + c0) =
                make_float2(acc[mf][nf][0], acc[mf][nf][1]);
            *reinterpret_cast<float2*>(C + (size_t)(r0 + 8) * TS + c0) =
                make_float2(acc[mf][nf][2], acc[mf][nf][3]);
        }
    }
}

// ============================================================================
// K2: in-place softmax over contiguous s axis. One block (256 thr) per row.
// ============================================================================
__global__ void __launch_bounds__(256)
softmax_kernel() {
    __shared__ float red[8];
    const size_t row = blockIdx.x;           // 0 .. NB*TQ-1
    float* S = g_scores + row * TS;
    const int tid = threadIdx.x;

    float x[8];
    float4 v0 = *reinterpret_cast<const float4*>(S + tid * 8);
    float4 v1 = *reinterpret_cast<const float4*>(S + tid * 8 + 4);
    x[0] = v0.x; x[1] = v0.y; x[2] = v0.z; x[3] = v0.w;
    x[4] = v1.x; x[5] = v1.y; x[6] = v1.z; x[7] = v1.w;

    float m = x[0];
    #pragma unroll
    for (int j = 1; j < 8; j++) m = fmaxf(m, x[j]);
    #pragma unroll
    for (int o = 16; o > 0; o >>= 1) m = fmaxf(m, __shfl_xor_sync(0xffffffffu, m, o));
    if ((tid & 31) == 0) red[tid >> 5] = m;
    __syncthreads();
    float mm = red[0];
    #pragma unroll
    for (int i = 1; i < 8; i++) mm = fmaxf(mm, red[i]);
    __syncthreads();

    float s = 0.f;
    #pragma unroll
    for (int j = 0; j < 8; j++) { x[j] = __expf(x[j] - mm); s += x[j]; }
    #pragma unroll
    for (int o = 16; o > 0; o >>= 1) s += __shfl_xor_sync(0xffffffffu, s, o);
    if ((tid & 31) == 0) red[tid >> 5] = s;
    __syncthreads();
    float tot = 0.f;
    #pragma unroll
    for (int i = 0; i < 8; i++) tot += red[i];
    float inv = 1.f / tot;

    #pragma unroll
    for (int j = 0; j < 8; j++) x[j] *= inv;
    *reinterpret_cast<float4*>(S + tid * 8)     = make_float4(x[0], x[1], x[2], x[3]);
    *reinterpret_cast<float4*>(S + tid * 8 + 4) = make_float4(x[4], x[5], x[6], x[7]);
}

// ============================================================================
// K3: context[q,h] = sum_s P[q,s] * enc[s,h]   (NN GEMM, 1xTF32)
// ============================================================================
__global__ void __launch_bounds__(256)
context_kernel(const float* __restrict__ enc, float* __restrict__ out) {
    __shared__ uint32_t As[128 * 20];
    __shared__ uint32_t Bs[16 * 136];

    const int bz = blockIdx.z;
    const float* A  = g_scores + (size_t)bz * TQ * TS;
    const float* Bm = enc + (size_t)bz * TS * HD;
    float* C = out + (size_t)bz * TQ * HD;
    const int bM = blockIdx.y * 128;
    const int bN = blockIdx.x * 128;

    const int tid  = threadIdx.x;
    const int lane = tid & 31;
    const int wid  = tid >> 5;
    const int wm   = (wid >> 2) * 64;
    const int wn   = (wid & 3) * 32;
    const int tg   = lane & 3;
    const int gp   = lane >> 2;

    float acc[4][4][4];
    #pragma unroll
    for (int i = 0; i < 4; i++)
        #pragma unroll
        for (int j = 0; j < 4; j++)
            #pragma unroll
            for (int k = 0; k < 4; k++) acc[i][j][k] = 0.f;

    for (int k0 = 0; k0 < TS; k0 += 16) {
        #pragma unroll
        for (int it = 0; it < 2; it++) {
            int slot = tid + it * 256;
            {   // A tile 128x16 (K-contiguous)
                int r = slot >> 2;
                int c = (slot & 3) * 4;
                float4 v = *reinterpret_cast<const float4*>(A + (size_t)(bM + r) * TS + k0 + c);
                As[r * 20 + c + 0] = f2tf(v.x);
                As[r * 20 + c + 1] = f2tf(v.y);
                As[r * 20 + c + 2] = f2tf(v.z);
                As[r * 20 + c + 3] = f2tf(v.w);
            }
            {   // B tile 16x128 (N-contiguous)
                int r = slot >> 5;                // 0..15
                int c = (slot & 31) * 4;          // 0..124
                float4 v = *reinterpret_cast<const float4*>(Bm + (size_t)(k0 + r) * HD + bN + c);
                Bs[r * 136 + c + 0] = f2tf(v.x);
                Bs[r * 136 + c + 1] = f2tf(v.y);
                Bs[r * 136 + c + 2] = f2tf(v.z);
                Bs[r * 136 + c + 3] = f2tf(v.w);
            }
        }
        __syncthreads();

        #pragma unroll
        for (int kk = 0; kk < 16; kk += 8) {
            uint32_t a[4][4], b[4][2];
            #pragma unroll
            for (int mf = 0; mf < 4; mf++) {
                int m = wm + mf * 16 + gp;
                a[mf][0] = As[m * 20 + kk + tg];
                a[mf][1] = As[(m + 8) * 20 + kk + tg];
                a[mf][2] = As[m * 20 + kk + tg + 4];
                a[mf][3] = As[(m + 8) * 20 + kk + tg + 4];
            }
            #pragma unroll
            for (int nf = 0; nf < 4; nf++) {
                int n = wn + nf * 8 + gp;
                b[nf][0] = Bs[(kk + tg) * 136 + n];
                b[nf][1] = Bs[(kk + tg + 4) * 136 + n];
            }
            #pragma unroll
            for (int mf = 0; mf < 4; mf++)
                #pragma unroll
                for (int nf = 0; nf < 4; nf++)
                    mma8(acc[mf][nf], a[mf], b[nf]);
        }
        __syncthreads();
    }

    #pragma unroll
    for (int mf = 0; mf < 4; mf++) {
        int r0 = bM + wm + mf * 16 + gp;
        #pragma unroll
        for (int nf = 0; nf < 4; nf++) {
            int c0 = bN + wn + nf * 8 + 2 * tg;
            *reinterpret_cast<float2*>(C + (size_t)r0 * HD + c0) =
                make_float2(acc[mf][nf][0], acc[mf][nf][1]);
            *reinterpret_cast<float2*>(C + (size_t)(r0 + 8) * HD + c0) =
                make_float2(acc[mf][nf][2], acc[mf][nf][3]);
        }
    }
}

extern "C" void kernel_launch(void* const* d_in, const int* in_sizes, int n_in,
                              void* d_out, int out_size) {
    const float* hidden = (const float*)d_in[0];   // [NB, TQ, HD]
    const float* enc    = (const float*)d_in[1];   // [NB, TS, HD]
    float* out = (float*)d_out;                    // [NB, TQ, HD]

    dim3 g1(TS / 128, TQ / 128, NB);
    scores_kernel<<<g1, 256>>>(hidden, enc);

    softmax_kernel<<<NB * TQ, 256>>>();

    dim3 g3(HD / 128, TQ / 128, NB);
    context_kernel<<<g3, 256>>>(enc, out);
}

// round 2
// speedup vs baseline: 1.5693x; 1.5693x over previous
#include <cuda_runtime.h>
#include <cuda_bf16.h>
#include <cstdint>

// Problem shape (fixed by reference setup_inputs)
static constexpr int NB = 16;
static constexpr int TQ = 2048;
static constexpr int TS = 2048;
static constexpr int HD = 1024;

// 256 MB scratch for scores / softmax probabilities: S[b][q][s] (s contiguous)
__device__ float g_scores[(size_t)NB * TQ * TS];

// ---------------------------------------------------------------------------
// helpers
// ---------------------------------------------------------------------------
__device__ __forceinline__ void mma16(float c[4], const uint32_t a[4], const uint32_t b[2]) {
    asm volatile(
        "mma.sync.aligned.m16n8k16.row.col.f32.bf16.bf16.f32 "
        "{%0,%1,%2,%3}, {%4,%5,%6,%7}, {%8,%9}, {%0,%1,%2,%3};\n"
        : "+f"(c[0]), "+f"(c[1]), "+f"(c[2]), "+f"(c[3])
        : "r"(a[0]), "r"(a[1]), "r"(a[2]), "r"(a[3]), "r"(b[0]), "r"(b[1]));
}

__device__ __forceinline__ void ldsm4(uint32_t& r0, uint32_t& r1, uint32_t& r2, uint32_t& r3,
                                      uint32_t addr) {
    asm volatile("ldmatrix.sync.aligned.m8n8.x4.shared.b16 {%0,%1,%2,%3}, [%4];"
                 : "=r"(r0), "=r"(r1), "=r"(r2), "=r"(r3) : "r"(addr));
}
__device__ __forceinline__ void ldsm2(uint32_t& r0, uint32_t& r1, uint32_t addr) {
    asm volatile("ldmatrix.sync.aligned.m8n8.x2.shared.b16 {%0,%1}, [%2];"
                 : "=r"(r0), "=r"(r1) : "r"(addr));
}
__device__ __forceinline__ void ldsm2t(uint32_t& r0, uint32_t& r1, uint32_t addr) {
    asm volatile("ldmatrix.sync.aligned.m8n8.x2.trans.shared.b16 {%0,%1}, [%2];"
                 : "=r"(r0), "=r"(r1) : "r"(addr));
}

// Split float4 into bf16 hi + bf16 mid (x ~= hi + mid, err ~ 2^-17 rel) and
// store 4 consecutive elements to each of two padded smem rows (8B stores).
__device__ __forceinline__ void cvt_store(__nv_bfloat16* ph, __nv_bfloat16* pm, float4 v) {
    __nv_bfloat162 h01 = __floats2bfloat162_rn(v.x, v.y);
    __nv_bfloat162 h23 = __floats2bfloat162_rn(v.z, v.w);
    float2 f01 = __bfloat1622float2(h01);
    float2 f23 = __bfloat1622float2(h23);
    __nv_bfloat162 m01 = __floats2bfloat162_rn(v.x - f01.x, v.y - f01.y);
    __nv_bfloat162 m23 = __floats2bfloat162_rn(v.z - f23.x, v.w - f23.y);
    uint2 uh, um;
    uh.x = *reinterpret_cast<uint32_t*>(&h01);
    uh.y = *reinterpret_cast<uint32_t*>(&h23);
    um.x = *reinterpret_cast<uint32_t*>(&m01);
    um.y = *reinterpret_cast<uint32_t*>(&m23);
    *reinterpret_cast<uint2*>(ph) = uh;
    *reinterpret_cast<uint2*>(pm) = um;
}

// ============================================================================
// K1: scores[q,s] = sum_h hid[q,h]*enc[s,h]  (NT). bf16x2-split, 3 MMA terms.
// Block 128x128, BK=32, 8 warps (2x4), warp tile 64x32.
// A rows: 32+8 pad bf16 (80B stride, conflict-free ldmatrix). B same layout.
// ============================================================================
__global__ void __launch_bounds__(256, 2)
scores_kernel(const float* __restrict__ hid, const float* __restrict__ enc) {
    __shared__ __nv_bfloat16 Ah[128 * 40], Am[128 * 40];
    __shared__ __nv_bfloat16 Bh[128 * 40], Bm[128 * 40];

    const int bz = blockIdx.z;
    const float* A  = hid + (size_t)bz * TQ * HD;
    const float* Bg = enc + (size_t)bz * TS * HD;
    float* C = g_scores + (size_t)bz * TQ * TS;
    const int bM = blockIdx.y * 128;
    const int bN = blockIdx.x * 128;

    const int tid  = threadIdx.x;
    const int lane = tid & 31;
    const int wid  = tid >> 5;
    const int wm   = (wid >> 2) * 64;
    const int wn   = (wid & 3) * 32;
    const int tg   = lane & 3;
    const int gp   = lane >> 2;

    const uint32_t AhS = (uint32_t)__cvta_generic_to_shared(Ah);
    const uint32_t AmS = (uint32_t)__cvta_generic_to_shared(Am);
    const uint32_t BhS = (uint32_t)__cvta_generic_to_shared(Bh);
    const uint32_t BmS = (uint32_t)__cvta_generic_to_shared(Bm);

    // ldmatrix per-lane base byte offsets
    const uint32_t aBase = (uint32_t)(wm + (lane & 15)) * 80u + (uint32_t)(lane >> 4) * 16u;
    const uint32_t bBase = (uint32_t)(wn + (lane & 7)) * 80u + (uint32_t)((lane >> 3) & 1) * 16u;

    // gmem load mapping: 4 float4 per thread per tensor per tile
    const int gr = tid >> 3;          // base row (0..31), +32 per i
    const int gc = (tid & 7) * 4;     // col (0..28)

    float acc[4][4][4];
    #pragma unroll
    for (int i = 0; i < 4; i++)
        #pragma unroll
        for (int j = 0; j < 4; j++)
            #pragma unroll
            for (int k = 0; k < 4; k++) acc[i][j][k] = 0.f;

    float4 sa[4], sb[4];
    #pragma unroll
    for (int i = 0; i < 4; i++) {
        sa[i] = *reinterpret_cast<const float4*>(A  + (size_t)(bM + gr + i * 32) * HD + gc);
        sb[i] = *reinterpret_cast<const float4*>(Bg + (size_t)(bN + gr + i * 32) * HD + gc);
    }

    for (int k0 = 0; k0 < HD; k0 += 32) {
        #pragma unroll
        for (int i = 0; i < 4; i++) {
            int r = gr + i * 32;
            cvt_store(&Ah[r * 40 + gc], &Am[r * 40 + gc], sa[i]);
            cvt_store(&Bh[r * 40 + gc], &Bm[r * 40 + gc], sb[i]);
        }
        __syncthreads();

        if (k0 + 32 < HD) {
            #pragma unroll
            for (int i = 0; i < 4; i++) {
                sa[i] = *reinterpret_cast<const float4*>(A  + (size_t)(bM + gr + i * 32) * HD + k0 + 32 + gc);
                sb[i] = *reinterpret_cast<const float4*>(Bg + (size_t)(bN + gr + i * 32) * HD + k0 + 32 + gc);
            }
        }

        #pragma unroll
        for (int kk = 0; kk < 32; kk += 16) {
            uint32_t bh[4][2], bm[4][2];
            #pragma unroll
            for (int nf = 0; nf < 4; nf++) {
                uint32_t off = bBase + (uint32_t)nf * (8u * 80u) + (uint32_t)kk * 2u;
                ldsm2(bh[nf][0], bh[nf][1], BhS + off);
                ldsm2(bm[nf][0], bm[nf][1], BmS + off);
            }
            #pragma unroll
            for (int mf = 0; mf < 4; mf++) {
                uint32_t ah[4], am[4];
                uint32_t off = aBase + (uint32_t)mf * (16u * 80u) + (uint32_t)kk * 2u;
                ldsm4(ah[0], ah[1], ah[2], ah[3], AhS + off);
                ldsm4(am[0], am[1], am[2], am[3], AmS + off);
                #pragma unroll
                for (int nf = 0; nf < 4; nf++) {
                    mma16(acc[mf][nf], ah, bh[nf]);   // hi*hi
                    mma16(acc[mf][nf], ah, bm[nf]);   // hi*mid
                    mma16(acc[mf][nf], am, bh[nf]);   // mid*hi
                }
            }
        }
        __syncthreads();
    }

    #pragma unroll
    for (int mf = 0; mf < 4; mf++) {
        int r0 = bM + wm + mf * 16 + gp;
        #pragma unroll
        for (int nf = 0; nf < 4; nf++) {
            int c0 = bN + wn + nf * 8 + 2 * tg;
            *reinterpret_cast<float2*>(C + (size_t)r0 * TS + c0) =
                make_float2(acc[mf][nf][0], acc[mf][nf][1]);
            *reinterpret_cast<float2*>(C + (size_t)(r0 + 8) * TS + c0) =
                make_float2(acc[mf][nf][2], acc[mf][nf][3]);
        }
    }
}

// ============================================================================
// K2: in-place softmax over contiguous s axis. One block (256 thr) per row.
// ============================================================================
__global__ void __launch_bounds__(256)
softmax_kernel() {
    __shared__ float red[8];
    const size_t row = blockIdx.x;
    float* S = g_scores + row * TS;
    const int tid = threadIdx.x;

    float x[8];
    float4 v0 = *reinterpret_cast<const float4*>(S + tid * 8);
    float4 v1 = *reinterpret_cast<const float4*>(S + tid * 8 + 4);
    x[0] = v0.x; x[1] = v0.y; x[2] = v0.z; x[3] = v0.w;
    x[4] = v1.x; x[5] = v1.y; x[6] = v1.z; x[7] = v1.w;

    float m = x[0];
    #pragma unroll
    for (int j = 1; j < 8; j++) m = fmaxf(m, x[j]);
    #pragma unroll
    for (int o = 16; o > 0; o >>= 1) m = fmaxf(m, __shfl_xor_sync(0xffffffffu, m, o));
    if ((tid & 31) == 0) red[tid >> 5] = m;
    __syncthreads();
    float mm = red[0];
    #pragma unroll
    for (int i = 1; i < 8; i++) mm = fmaxf(mm, red[i]);
    __syncthreads();

    float s = 0.f;
    #pragma unroll
    for (int j = 0; j < 8; j++) { x[j] = __expf(x[j] - mm); s += x[j]; }
    #pragma unroll
    for (int o = 16; o > 0; o >>= 1) s += __shfl_xor_sync(0xffffffffu, s, o);
    if ((tid & 31) == 0) red[tid >> 5] = s;
    __syncthreads();
    float tot = 0.f;
    #pragma unroll
    for (int i = 0; i < 8; i++) tot += red[i];
    float inv = 1.f / tot;

    #pragma unroll
    for (int j = 0; j < 8; j++) x[j] *= inv;
    *reinterpret_cast<float4*>(S + tid * 8)     = make_float4(x[0], x[1], x[2], x[3]);
    *reinterpret_cast<float4*>(S + tid * 8 + 4) = make_float4(x[4], x[5], x[6], x[7]);
}

// ============================================================================
// K3: context[q,h] = sum_s P[q,s]*enc[s,h]  (NN). bf16x2-split, 3 MMA terms.
// A (P) k-contig like K1-A; B (enc) n-contig -> trans ldmatrix, 272B rows.
// ============================================================================
__global__ void __launch_bounds__(256, 2)
context_kernel(const float* __restrict__ enc, float* __restrict__ out) {
    __shared__ __nv_bfloat16 Ah[128 * 40], Am[128 * 40];
    __shared__ __nv_bfloat16 Bh[32 * 136], Bm[32 * 136];

    const int bz = blockIdx.z;
    const float* A  = g_scores + (size_t)bz * TQ * TS;
    const float* Bg = enc + (size_t)bz * TS * HD;
    float* C = out + (size_t)bz * TQ * HD;
    const int bM = blockIdx.y * 128;
    const int bN = blockIdx.x * 128;

    const int tid  = threadIdx.x;
    const int lane = tid & 31;
    const int wid  = tid >> 5;
    const int wm   = (wid >> 2) * 64;
    const int wn   = (wid & 3) * 32;
    const int tg   = lane & 3;
    const int gp   = lane >> 2;

    const uint32_t AhS = (uint32_t)__cvta_generic_to_shared(Ah);
    const uint32_t AmS = (uint32_t)__cvta_generic_to_shared(Am);
    const uint32_t BhS = (uint32_t)__cvta_generic_to_shared(Bh);
    const uint32_t BmS = (uint32_t)__cvta_generic_to_shared(Bm);

    const uint32_t aBase = (uint32_t)(wm + (lane & 15)) * 80u + (uint32_t)(lane >> 4) * 16u;
    // trans ldmatrix base: row = kk + (lane&15), col = wn + nf*8
    const uint32_t tBase = (uint32_t)(lane & 15) * 272u + (uint32_t)wn * 2u;

    // A gmem mapping (128x32 tile): 4 float4/thread
    const int gar = tid >> 3;
    const int gac = (tid & 7) * 4;
    // B gmem mapping (32x128 tile): 4 float4/thread
    const int gbr = tid >> 5;            // +8 per i
    const int gbc = (tid & 31) * 4;

    float acc[4][4][4];
    #pragma unroll
    for (int i = 0; i < 4; i++)
        #pragma unroll
        for (int j = 0; j < 4; j++)
            #pragma unroll
            for (int k = 0; k < 4; k++) acc[i][j][k] = 0.f;

    float4 sa[4], sb[4];
    #pragma unroll
    for (int i = 0; i < 4; i++) {
        sa[i] = *reinterpret_cast<const float4*>(A  + (size_t)(bM + gar + i * 32) * TS + gac);
        sb[i] = *reinterpret_cast<const float4*>(Bg + (size_t)(gbr + i * 8) * HD + bN + gbc);
    }

    for (int k0 = 0; k0 < TS; k0 += 32) {
        #pragma unroll
        for (int i = 0; i < 4; i++) {
            int ra = gar + i * 32;
            cvt_store(&Ah[ra * 40 + gac], &Am[ra * 40 + gac], sa[i]);
            int rb = gbr + i * 8;
            cvt_store(&Bh[rb * 136 + gbc], &Bm[rb * 136 + gbc], sb[i]);
        }
        __syncthreads();

        if (k0 + 32 < TS) {
            #pragma unroll
            for (int i = 0; i < 4; i++) {
                sa[i] = *reinterpret_cast<const float4*>(A  + (size_t)(bM + gar + i * 32) * TS + k0 + 32 + gac);
                sb[i] = *reinterpret_cast<const float4*>(Bg + (size_t)(k0 + 32 + gbr + i * 8) * HD + bN + gbc);
            }
        }

        #pragma unroll
        for (int kk = 0; kk < 32; kk += 16) {
            uint32_t bh[4][2], bm[4][2];
            #pragma unroll
            for (int nf = 0; nf < 4; nf++) {
                uint32_t off = tBase + (uint32_t)kk * 272u + (uint32_t)nf * 16u;
                ldsm2t(bh[nf][0], bh[nf][1], BhS + off);
                ldsm2t(bm[nf][0], bm[nf][1], BmS + off);
            }
            #pragma unroll
            for (int mf = 0; mf < 4; mf++) {
                uint32_t ah[4], am[4];
                uint32_t off = aBase + (uint32_t)mf * (16u * 80u) + (uint32_t)kk * 2u;
                ldsm4(ah[0], ah[1], ah[2], ah[3], AhS + off);
                ldsm4(am[0], am[1], am[2], am[3], AmS + off);
                #pragma unroll
                for (int nf = 0; nf < 4; nf++) {
                    mma16(acc[mf][nf], ah, bh[nf]);
                    mma16(acc[mf][nf], ah, bm[nf]);
                    mma16(acc[mf][nf], am, bh[nf]);
                }
            }
        }
        __syncthreads();
    }

    #pragma unroll
    for (int mf = 0; mf < 4; mf++) {
        int r0 = bM + wm + mf * 16 + gp;
        #pragma unroll
        for (int nf = 0; nf < 4; nf++) {
            int c0 = bN + wn + nf * 8 + 2 * tg;
            *reinterpret_cast<float2*>(C + (size_t)r0 * HD + c0) =
                make_float2(acc[mf][nf][0], acc[mf][nf][1]);
            *reinterpret_cast<float2*>(C + (size_t)(r0 + 8) * HD + c0) =
                make_float2(acc[mf][nf][2], acc[mf][nf][3]);
        }
    }
}

extern "C" void kernel_launch(void* const* d_in, const int* in_sizes, int n_in,
                              void* d_out, int out_size) {
    const float* hidden = (const float*)d_in[0];   // [NB, TQ, HD]
    const float* enc    = (const float*)d_in[1];   // [NB, TS, HD]
    float* out = (float*)d_out;                    // [NB, TQ, HD]

    dim3 g1(TS / 128, TQ / 128, NB);
    scores_kernel<<<g1, 256>>>(hidden, enc);

    softmax_kernel<<<NB * TQ, 256>>>();

    dim3 g3(HD / 128, TQ / 128, NB);
    context_kernel<<<g3, 256>>>(enc, out);
}